// round 13
// baseline (speedup 1.0000x reference)
#include <cuda_runtime.h>
#include <cuda_bf16.h>
#include <math.h>
#include <cstdint>

#define B_MAX 2048
#define LMAX 100
#define DDIM 256
#define POS_DIM 50

__device__ int   g_offs[B_MAX];
__device__ int   g_perm[B_MAX];
__device__ int   g_total_rows;
__device__ int   g_rowmap[(size_t)B_MAX * LMAX];
__device__ float g_abs_vals[LMAX];
__device__ float g_rel_vals[32];
__device__ float g_docs[(size_t)B_MAX * DDIM];
__device__ float g_u[(size_t)B_MAX * DDIM];
__device__ float g_G[(size_t)B_MAX * LMAX * DDIM];
__device__ __nv_bfloat16 g_W1h[DDIM * DDIM], g_W1l[DDIM * DDIM]; // fc_w
__device__ __nv_bfloat16 g_W2h[DDIM * DDIM], g_W2l[DDIM * DDIM]; // W_sal
__device__ __nv_bfloat16 g_W3h[DDIM * DDIM], g_W3l[DDIM * DDIM]; // W_nov^T

__device__ __forceinline__ uint32_t smem_u32(const void* p) {
    uint32_t a;
    asm("{ .reg .u64 t; cvta.to.shared.u64 t, %1; cvt.u32.u64 %0, t; }"
        : "=r"(a) : "l"(p));
    return a;
}
#define LDSM4(r, addr) \
    asm volatile("ldmatrix.sync.aligned.m8n8.x4.shared.b16 {%0,%1,%2,%3}, [%4];" \
        : "=r"((r)[0]), "=r"((r)[1]), "=r"((r)[2]), "=r"((r)[3]) : "r"(addr))
#define MMA_BF16(c, a, b0, b1) \
    asm volatile("mma.sync.aligned.m16n8k16.row.col.f32.bf16.bf16.f32 " \
        "{%0,%1,%2,%3},{%4,%5,%6,%7},{%8,%9},{%0,%1,%2,%3};" \
        : "+f"((c)[0]), "+f"((c)[1]), "+f"((c)[2]), "+f"((c)[3]) \
        : "r"((a)[0]), "r"((a)[1]), "r"((a)[2]), "r"((a)[3]), "r"(b0), "r"(b1))
#define CP_ASYNC16(dst, src) \
    asm volatile("cp.async.cg.shared.global [%0], [%1], 16;" \
                 :: "r"(dst), "l"(src))
#define CP_COMMIT() asm volatile("cp.async.commit_group;" ::: "memory")
#define CP_WAIT(n)  asm volatile("cp.async.wait_group %0;" :: "n"(n) : "memory")

__device__ __forceinline__ void split_store(char* hi_p, char* lo_p, float2 v) {
    __nv_bfloat162 h = __float22bfloat162_rn(v);
    float2 f = __bfloat1622float2(h);
    __nv_bfloat162 l = __float22bfloat162_rn(make_float2(v.x - f.x, v.y - f.y));
    *(__nv_bfloat162*)hi_p = h;
    *(__nv_bfloat162*)lo_p = l;
}

// ===== scan: offsets, total, global length sort, position dots =====
__global__ void scan_kernel(const int* __restrict__ dl, int B,
                            const float* __restrict__ abs_e,
                            const float* __restrict__ rel_e,
                            const float* __restrict__ w_abs,
                            const float* __restrict__ w_rel) {
    __shared__ int sh[B_MAX];
    __shared__ int wsum[8];
    __shared__ int hist[LMAX + 1];
    __shared__ int hstart[LMAX + 1];
    int t = threadIdx.x;
    for (int i = t; i < B_MAX; i += 256) sh[i] = (i < B) ? dl[i] : 0;
    if (t <= LMAX) hist[t] = 0;
    __syncthreads();
    int base = t * 8;
    int ex[8]; int run = 0;
#pragma unroll
    for (int k = 0; k < 8; k++) { ex[k] = run; run += sh[base + k]; }
    int lane = t & 31, w = t >> 5;
    int inc = run;
#pragma unroll
    for (int st = 1; st < 32; st <<= 1) {
        int x = __shfl_up_sync(0xffffffffu, inc, st);
        if (lane >= st) inc += x;
    }
    if (lane == 31) wsum[w] = inc;
    for (int i = t; i < B; i += 256) {
        int d = sh[i]; d = (d < 0) ? 0 : (d > LMAX ? LMAX : d);
        atomicAdd(&hist[d], 1);
    }
    __syncthreads();
    int wbase = 0;
    for (int i = 0; i < w; i++) wbase += wsum[i];
    int chunk_ex = wbase + inc - run;
#pragma unroll
    for (int k = 0; k < 8; k++)
        if (base + k < B) g_offs[base + k] = chunk_ex + ex[k];
    if (t == 0) {
        int tot = 0;
        for (int i = 0; i < 8; i++) tot += wsum[i];
        g_total_rows = tot;
        int running = 0;
        for (int d = LMAX; d >= 0; d--) { hstart[d] = running; running += hist[d]; }
    }
    __syncthreads();
    for (int i = t; i < B; i += 256) {
        int d = sh[i]; d = (d < 0) ? 0 : (d > LMAX ? LMAX : d);
        int pos = atomicAdd(&hstart[d], 1);
        g_perm[pos] = i;
    }
    if (t < LMAX) {
        float a = 0.f;
        for (int i = 0; i < POS_DIM; i++) a += abs_e[t * POS_DIM + i] * w_abs[i];
        g_abs_vals[t] = a;
    } else if (t >= 128 && t < 153) {
        int s = t - 128;
        float a = 0.f;
        for (int i = 0; i < POS_DIM; i++) a += rel_e[s * POS_DIM + i] * w_rel[i];
        g_rel_vals[s] = a;
    }
}

// ===== prep_all: W prep (y=0..2) + rowmap expand (y=3) =====
__global__ void prep_all_kernel(const float* __restrict__ fc_w,
                                const float* __restrict__ W_sal,
                                const float* __restrict__ W_nov,
                                const int* __restrict__ dl, int B) {
    int idx = blockIdx.x * 256 + threadIdx.x;
    int y = blockIdx.y;
    if (y == 0) {
        int n = idx >> 8, k = idx & 255;
        float w = W_nov[k * DDIM + n];
        __nv_bfloat16 h = __float2bfloat16_rn(w);
        g_W3h[n * DDIM + k] = h;
        g_W3l[n * DDIM + k] = __float2bfloat16_rn(w - __bfloat162float(h));
    } else if (y == 1) {
        float w = fc_w[idx];
        __nv_bfloat16 h = __float2bfloat16_rn(w);
        g_W1h[idx] = h;
        g_W1l[idx] = __float2bfloat16_rn(w - __bfloat162float(h));
    } else if (y == 2) {
        float w = W_sal[idx];
        __nv_bfloat16 h = __float2bfloat16_rn(w);
        g_W2h[idx] = h;
        g_W2l[idx] = __float2bfloat16_rn(w - __bfloat162float(h));
    } else {
        int b = idx >> 5, j = idx & 31;
        if (b < B) {
            int n = dl[b], off = g_offs[b];
            for (int k = j; k < n; k += 32)
                g_rowmap[off + k] = b * LMAX + k;
        }
    }
}

// ===== masked mean (float4, 4 rows in flight) =====
__global__ void __launch_bounds__(256) mean_kernel(const float* __restrict__ sent,
                                                   const int* __restrict__ dl) {
    __shared__ float4 part[4][64];
    int b = blockIdx.x, tid = threadIdx.x;
    int n = dl[b];
    int c4 = tid & 63, rq = tid >> 6;
    const float4* sp = (const float4*)(sent + (size_t)b * LMAX * DDIM);
    float4 a = make_float4(0.f, 0.f, 0.f, 0.f);
    for (int t = rq; t < n; t += 4) {
        float4 v = sp[t * 64 + c4];
        a.x += v.x; a.y += v.y; a.z += v.z; a.w += v.w;
    }
    part[rq][c4] = a;
    __syncthreads();
    if (tid < 64) {
        float4 r0 = part[0][tid], r1 = part[1][tid], r2 = part[2][tid], r3 = part[3][tid];
        float inv = __fdiv_rn(1.f, (float)n);
        float4 o;
        o.x = (r0.x + r1.x + r2.x + r3.x) * inv;
        o.y = (r0.y + r1.y + r2.y + r3.y) * inv;
        o.z = (r0.z + r1.z + r2.z + r3.z) * inv;
        o.w = (r0.w + r1.w + r2.w + r3.w) * inv;
        *(float4*)&g_docs[(size_t)b * DDIM + tid * 4] = o;
    }
}

// ===== fused doc+u kernel (unchanged) =====
#define U_DOC_HI 0
#define U_DOC_LO 33792
#define U_A1_HI  67584
#define U_A1_LO  76800
#define U_B_HI   86016
#define U_B_LO   104448
#define U_TOTAL  122880

__global__ void __launch_bounds__(256) ugemm_kernel(
    const float* __restrict__ docs,
    const __nv_bfloat16* __restrict__ W1h, const __nv_bfloat16* __restrict__ W1l,
    const __nv_bfloat16* __restrict__ W2h, const __nv_bfloat16* __restrict__ W2l,
    const float* __restrict__ fc_b, const float* __restrict__ w_content,
    float* __restrict__ u_out, int M)
{
    const int m0 = blockIdx.x * 64;
    if (m0 >= M) return;
    extern __shared__ char sm[];
    const uint32_t sb = smem_u32(sm);
    const int tid = threadIdx.x, lane = tid & 31, wid = tid >> 5;
    const int wm = wid & 1, wn = wid >> 1;
    const int alr = lane & 15, alc = (lane & 16) >> 1;
    const int blr = (lane & 7) | ((lane >> 1) & 8), blc = lane & 8;
    const int gID = lane >> 2, tg = lane & 3;
    const uint32_t a1_base = sb + U_A1_HI + (uint32_t)((wm * 32 + alr) * 144 + alc * 2);
    const uint32_t a2_base = sb + U_DOC_HI + (uint32_t)((wm * 32 + alr) * 528 + alc * 2);
    const uint32_t b_base  = sb + U_B_HI + (uint32_t)((wn * 32 + blr) * 144 + blc * 2);

    for (int nh = 0; nh < 2; nh++) {
        float c[2][4][4];
#pragma unroll
        for (int mt = 0; mt < 2; mt++)
#pragma unroll
            for (int nf = 0; nf < 4; nf++)
#pragma unroll
                for (int r = 0; r < 4; r++) c[mt][nf][r] = 0.f;

        for (int ch = 0; ch < 4; ch++) {
            __syncthreads();
#pragma unroll
            for (int i = 0; i < 4; i++) {
                int idx = tid + i * 256;
                int m = idx >> 4, kq = idx & 15;
                float4 v = make_float4(0.f, 0.f, 0.f, 0.f);
                if (m0 + m < M)
                    v = *(const float4*)&docs[(size_t)(m0 + m) * DDIM + ch * 64 + kq * 4];
                split_store(sm + U_A1_HI + m * 144 + kq * 8,
                            sm + U_A1_LO + m * 144 + kq * 8, make_float2(v.x, v.y));
                split_store(sm + U_A1_HI + m * 144 + kq * 8 + 4,
                            sm + U_A1_LO + m * 144 + kq * 8 + 4, make_float2(v.z, v.w));
            }
#pragma unroll
            for (int i = 0; i < 4; i++) {
                int idx = tid + i * 256;
                int n = idx >> 3, k4 = idx & 7;
                *(float4*)(sm + U_B_HI + n * 144 + k4 * 16) =
                    *(const float4*)&W1h[(size_t)(nh * 128 + n) * DDIM + ch * 64 + k4 * 8];
                *(float4*)(sm + U_B_LO + n * 144 + k4 * 16) =
                    *(const float4*)&W1l[(size_t)(nh * 128 + n) * DDIM + ch * 64 + k4 * 8];
            }
            __syncthreads();
#pragma unroll
            for (int ks = 0; ks < 4; ks++) {
                uint32_t ah[2][4], al[2][4], bh[2][4], bl[2][4];
#pragma unroll
                for (int mt = 0; mt < 2; mt++) {
                    LDSM4(ah[mt], a1_base + mt * 2304 + ks * 32);
                    LDSM4(al[mt], a1_base + 9216u + mt * 2304 + ks * 32);
                }
#pragma unroll
                for (int nt = 0; nt < 2; nt++) {
                    LDSM4(bh[nt], b_base + nt * 2304 + ks * 32);
                    LDSM4(bl[nt], b_base + 18432u + nt * 2304 + ks * 32);
                }
#pragma unroll
                for (int mt = 0; mt < 2; mt++)
#pragma unroll
                    for (int nf = 0; nf < 4; nf++) {
                        MMA_BF16(c[mt][nf], ah[mt], bh[nf >> 1][(nf & 1) * 2],
                                 bh[nf >> 1][(nf & 1) * 2 + 1]);
                        MMA_BF16(c[mt][nf], ah[mt], bl[nf >> 1][(nf & 1) * 2],
                                 bl[nf >> 1][(nf & 1) * 2 + 1]);
                        MMA_BF16(c[mt][nf], al[mt], bh[nf >> 1][(nf & 1) * 2],
                                 bh[nf >> 1][(nf & 1) * 2 + 1]);
                    }
            }
        }
#pragma unroll
        for (int mt = 0; mt < 2; mt++)
#pragma unroll
            for (int nf = 0; nf < 4; nf++) {
                int row = wm * 32 + mt * 16 + gID;
                int kcol = nh * 128 + wn * 32 + nf * 8 + tg * 2;
                float b0v = fc_b[kcol], b1v = fc_b[kcol + 1];
                float2 v0 = make_float2(tanhf(c[mt][nf][0] + b0v),
                                        tanhf(c[mt][nf][1] + b1v));
                split_store(sm + U_DOC_HI + row * 528 + kcol * 2,
                            sm + U_DOC_LO + row * 528 + kcol * 2, v0);
                float2 v1 = make_float2(tanhf(c[mt][nf][2] + b0v),
                                        tanhf(c[mt][nf][3] + b1v));
                split_store(sm + U_DOC_HI + (row + 8) * 528 + kcol * 2,
                            sm + U_DOC_LO + (row + 8) * 528 + kcol * 2, v1);
            }
    }
    __syncthreads();

    for (int nh = 0; nh < 2; nh++) {
        float c[2][4][4];
#pragma unroll
        for (int mt = 0; mt < 2; mt++)
#pragma unroll
            for (int nf = 0; nf < 4; nf++)
#pragma unroll
                for (int r = 0; r < 4; r++) c[mt][nf][r] = 0.f;

        for (int ch = 0; ch < 4; ch++) {
            __syncthreads();
#pragma unroll
            for (int i = 0; i < 4; i++) {
                int idx = tid + i * 256;
                int n = idx >> 3, k4 = idx & 7;
                *(float4*)(sm + U_B_HI + n * 144 + k4 * 16) =
                    *(const float4*)&W2h[(size_t)(nh * 128 + n) * DDIM + ch * 64 + k4 * 8];
                *(float4*)(sm + U_B_LO + n * 144 + k4 * 16) =
                    *(const float4*)&W2l[(size_t)(nh * 128 + n) * DDIM + ch * 64 + k4 * 8];
            }
            __syncthreads();
#pragma unroll
            for (int ks = 0; ks < 4; ks++) {
                const uint32_t ka = (uint32_t)((ch * 64 + ks * 16) * 2);
                uint32_t ah[2][4], al[2][4], bh[2][4], bl[2][4];
#pragma unroll
                for (int mt = 0; mt < 2; mt++) {
                    LDSM4(ah[mt], a2_base + mt * 8448 + ka);
                    LDSM4(al[mt], a2_base + 33792u + mt * 8448 + ka);
                }
#pragma unroll
                for (int nt = 0; nt < 2; nt++) {
                    LDSM4(bh[nt], b_base + nt * 2304 + ks * 32);
                    LDSM4(bl[nt], b_base + 18432u + nt * 2304 + ks * 32);
                }
#pragma unroll
                for (int mt = 0; mt < 2; mt++)
#pragma unroll
                    for (int nf = 0; nf < 4; nf++) {
                        MMA_BF16(c[mt][nf], ah[mt], bh[nf >> 1][(nf & 1) * 2],
                                 bh[nf >> 1][(nf & 1) * 2 + 1]);
                        MMA_BF16(c[mt][nf], ah[mt], bl[nf >> 1][(nf & 1) * 2],
                                 bl[nf >> 1][(nf & 1) * 2 + 1]);
                        MMA_BF16(c[mt][nf], al[mt], bh[nf >> 1][(nf & 1) * 2],
                                 bh[nf >> 1][(nf & 1) * 2 + 1]);
                    }
            }
        }
#pragma unroll
        for (int mt = 0; mt < 2; mt++)
#pragma unroll
            for (int nf = 0; nf < 4; nf++) {
                int row = wm * 32 + mt * 16 + gID;
                int n = nh * 128 + wn * 32 + nf * 8 + tg * 2;
                float w0 = w_content[n], w1 = w_content[n + 1];
                if (m0 + row < M)
                    *(float2*)&u_out[(size_t)(m0 + row) * DDIM + n] =
                        make_float2(c[mt][nf][0] + w0, c[mt][nf][1] + w1);
                if (m0 + row + 8 < M)
                    *(float2*)&u_out[(size_t)(m0 + row + 8) * DDIM + n] =
                        make_float2(c[mt][nf][2] + w0, c[mt][nf][3] + w1);
            }
    }
}

// ===== big GEMM: 128x128 CTA tile, 64x32 warp tile, cp.async dbuf B =====
#define AS_HI 0
#define AS_LO 18432
#define BBUF  36864              // two buffers of 36864 (hi 18432 + lo 18432)
#define GSM3_TOTAL 110592

__global__ void __launch_bounds__(256, 2) gemm3_kernel(
    const float* __restrict__ A, const __nv_bfloat16* __restrict__ Bh,
    const __nv_bfloat16* __restrict__ Bl, float* __restrict__ C,
    const int* __restrict__ row_map)
{
    const int M = g_total_rows;
    const int gm0 = blockIdx.x * 128;
    if (gm0 >= M) return;
    extern __shared__ char sm[];
    const uint32_t sb = smem_u32(sm);
    const int tid = threadIdx.x, lane = tid & 31, wid = tid >> 5;
    const int wm = wid & 1, wn = wid >> 1;
    const int n0 = blockIdx.y * 128;

    const int alr = lane & 15;
    const int alc = (lane & 16) >> 1;
    const int blr = (lane & 7) | ((lane >> 1) & 8);
    const int blc = lane & 8;
    const uint32_t a_base = sb + AS_HI + (uint32_t)(((wm * 64 + alr) * 72 + alc) * 2);
    const uint32_t b_off  = (uint32_t)(((wn * 32 + blr) * 72 + blc) * 2);

    // B-stage cp.async coordinates (per thread: 4 hi + 4 lo lines)
    const int bn = tid >> 3, bk4 = tid & 7;   // used with +64*i rows

    // prologue: issue B chunk 0 into buffer 0
#pragma unroll
    for (int i = 0; i < 2; i++) {
        int n = bn + i * 32;   // wait: need 128 rows x 8 k4 = 1024 lines per buf
        (void)n;
    }
    {
        uint32_t dst = sb + BBUF;
#pragma unroll
        for (int i = 0; i < 4; i++) {
            int idx = tid + i * 256;             // 1024
            int n = idx >> 3, k4 = idx & 7;
            CP_ASYNC16(dst + n * 144 + k4 * 16,
                       (const void*)&Bh[(size_t)(n0 + n) * DDIM + k4 * 8]);
            CP_ASYNC16(dst + 18432u + n * 144 + k4 * 16,
                       (const void*)&Bl[(size_t)(n0 + n) * DDIM + k4 * 8]);
        }
        CP_COMMIT();
    }

    float c[4][4][4];
#pragma unroll
    for (int mt = 0; mt < 4; mt++)
#pragma unroll
        for (int nf = 0; nf < 4; nf++)
#pragma unroll
            for (int r = 0; r < 4; r++) c[mt][nf][r] = 0.f;

    for (int ch = 0; ch < 4; ch++) {
        const int k0 = ch * 64;
        const int cur = ch & 1;
        if (ch > 0) __syncthreads();   // prev MMA done reading A + old B buf

        // issue next B chunk into the other buffer (now free)
        if (ch < 3) {
            uint32_t dst = sb + BBUF + (cur ^ 1) * 36864u;
            const int kn = (ch + 1) * 64;
#pragma unroll
            for (int i = 0; i < 4; i++) {
                int idx = tid + i * 256;
                int n = idx >> 3, k4 = idx & 7;
                CP_ASYNC16(dst + n * 144 + k4 * 16,
                           (const void*)&Bh[(size_t)(n0 + n) * DDIM + kn + k4 * 8]);
                CP_ASYNC16(dst + 18432u + n * 144 + k4 * 16,
                           (const void*)&Bl[(size_t)(n0 + n) * DDIM + kn + k4 * 8]);
            }
            CP_COMMIT();
        }

        // stage A chunk (fp32 -> bf16 hi/lo), overlaps in-flight cp.async
#pragma unroll
        for (int i = 0; i < 8; i++) {
            int idx = tid + i * 256;
            int m = idx >> 4, kq = idx & 15;
            float4 v = make_float4(0.f, 0.f, 0.f, 0.f);
            int gm = gm0 + m;
            if (gm < M)
                v = *(const float4*)&A[(size_t)row_map[gm] * DDIM + k0 + kq * 4];
            split_store(sm + AS_HI + m * 144 + kq * 8,
                        sm + AS_LO + m * 144 + kq * 8, make_float2(v.x, v.y));
            split_store(sm + AS_HI + m * 144 + kq * 8 + 4,
                        sm + AS_LO + m * 144 + kq * 8 + 4, make_float2(v.z, v.w));
        }

        // wait for B chunk ch (leave the just-issued group in flight)
        if (ch < 3) { CP_WAIT(1); } else { CP_WAIT(0); }
        __syncthreads();

        const uint32_t b_base = sb + BBUF + cur * 36864u + b_off;
#pragma unroll
        for (int ks = 0; ks < 4; ks++) {
            uint32_t ah[4][4], al[4][4], bh[2][4], bl[2][4];
#pragma unroll
            for (int mt = 0; mt < 4; mt++)
                LDSM4(ah[mt], a_base + mt * 2304 + ks * 32);
#pragma unroll
            for (int nt = 0; nt < 2; nt++) {
                LDSM4(bh[nt], b_base + nt * 2304 + ks * 32);
                LDSM4(bl[nt], b_base + 18432u + nt * 2304 + ks * 32);
            }
#pragma unroll
            for (int mt = 0; mt < 4; mt++)
#pragma unroll
                for (int nf = 0; nf < 4; nf++) {
                    MMA_BF16(c[mt][nf], ah[mt], bh[nf >> 1][(nf & 1) * 2],
                             bh[nf >> 1][(nf & 1) * 2 + 1]);
                    MMA_BF16(c[mt][nf], ah[mt], bl[nf >> 1][(nf & 1) * 2],
                             bl[nf >> 1][(nf & 1) * 2 + 1]);
                }
#pragma unroll
            for (int mt = 0; mt < 4; mt++)
                LDSM4(al[mt], a_base + 18432u + mt * 2304 + ks * 32);
#pragma unroll
            for (int mt = 0; mt < 4; mt++)
#pragma unroll
                for (int nf = 0; nf < 4; nf++)
                    MMA_BF16(c[mt][nf], al[mt], bh[nf >> 1][(nf & 1) * 2],
                             bh[nf >> 1][(nf & 1) * 2 + 1]);
        }
    }
    __syncthreads();

    float* stage = (float*)sm;
    const int gID = lane >> 2, tg = lane & 3;
    for (int mh = 0; mh < 2; mh++) {
        if (wm == mh) {
#pragma unroll
            for (int mt = 0; mt < 4; mt++)
#pragma unroll
                for (int nf = 0; nf < 4; nf++) {
                    int r = mt * 16 + gID;
                    int cc = wn * 32 + nf * 8 + tg * 2;
                    *(float2*)&stage[r * 132 + cc] =
                        make_float2(c[mt][nf][0], c[mt][nf][1]);
                    *(float2*)&stage[(r + 8) * 132 + cc] =
                        make_float2(c[mt][nf][2], c[mt][nf][3]);
                }
        }
        __syncthreads();
#pragma unroll
        for (int i = 0; i < 8; i++) {
            int idx = tid + i * 256;
            int r = idx >> 5, c4 = idx & 31;
            int grow = gm0 + mh * 64 + r;
            if (grow < M)
                *(float4*)&C[(size_t)grow * DDIM + n0 + c4 * 4] =
                    *(float4*)&stage[r * 132 + c4 * 4];
        }
        __syncthreads();
    }
    (void)bn; (void)bk4;
}

// ===== fast tanh =====
__device__ __forceinline__ float fast_tanh(float x) {
    float e = __expf(2.f * x);
    return 1.f - __fdividef(2.f, e + 1.f);
}

// ===== warp-per-doc recurrence (length-sorted), 2-pair prefetch =====
__global__ void __launch_bounds__(256) recur_kernel(
    const float* __restrict__ sent, const float* __restrict__ bias,
    const int* __restrict__ doc_lens, int B, float* __restrict__ out)
{
    __shared__ float sA[LMAX];
    __shared__ float sR[32];
    const int tid = threadIdx.x, lane = tid & 31, wid = tid >> 5;
    if (tid < LMAX) sA[tid] = g_abs_vals[tid];
    if (tid < 32) sR[tid] = g_rel_vals[tid];
    __syncthreads();

    const int gid = blockIdx.x * 8 + wid;
    if (gid >= B) return;
    const int b = g_perm[gid];
    const int dl = doc_lens[b];
    const float dlf = (float)dl;
    const int off = g_offs[b];
    const float* hp = sent + (size_t)b * LMAX * DDIM + lane * 8;
    const float* gp = g_G + (size_t)off * DDIM + lane * 8;
    const float b0 = bias[0];

    float u[8];
    {
        const float* up = g_u + (size_t)b * DDIM + lane * 8;
        *(float4*)u = *(const float4*)up;
        *(float4*)(u + 4) = *(const float4*)(up + 4);
    }
    float s[8] = {0.f, 0.f, 0.f, 0.f, 0.f, 0.f, 0.f, 0.f};

    auto do_step = [&](int t, const float* hc, const float* gc) {
        float v0 = 0.f, v1 = 0.f;
#pragma unroll
        for (int e = 0; e < 4; e++)
            v0 += hc[e] * u[e] - gc[e] * fast_tanh(s[e]);
#pragma unroll
        for (int e = 4; e < 8; e++)
            v1 += hc[e] * u[e] - gc[e] * fast_tanh(s[e]);
        float v = v0 + v1;
#pragma unroll
        for (int st = 16; st; st >>= 1) v += __shfl_xor_sync(0xffffffffu, v, st);
        int ri = (int)rintf(__fdiv_rn((float)(t + 1) * 9.0f, dlf));
        float x = v + sA[t] + sR[ri] + b0;
        float p = __fdividef(1.f, 1.f + __expf(-x));
#pragma unroll
        for (int e = 0; e < 8; e++) s[e] = fmaf(p, hc[e], s[e]);
        if (lane == 0) out[off + t] = p;
    };

    float h0[8], g0[8], h1[8], g1[8];
    *(float4*)h0 = *(const float4*)hp;
    *(float4*)(h0 + 4) = *(const float4*)(hp + 4);
    *(float4*)g0 = *(const float4*)gp;
    *(float4*)(g0 + 4) = *(const float4*)(gp + 4);
    if (dl > 1) {
        *(float4*)h1 = *(const float4*)(hp + DDIM);
        *(float4*)(h1 + 4) = *(const float4*)(hp + DDIM + 4);
        *(float4*)g1 = *(const float4*)(gp + DDIM);
        *(float4*)(g1 + 4) = *(const float4*)(gp + DDIM + 4);
    }

    int t = 0;
    for (; t + 1 < dl; t += 2) {
        float h2[8], g2[8], h3[8], g3[8];
        if (t + 2 < dl) {
            const float* hq = hp + (size_t)(t + 2) * DDIM;
            const float* gq = gp + (size_t)(t + 2) * DDIM;
            *(float4*)h2 = *(const float4*)hq;
            *(float4*)(h2 + 4) = *(const float4*)(hq + 4);
            *(float4*)g2 = *(const float4*)gq;
            *(float4*)(g2 + 4) = *(const float4*)(gq + 4);
        }
        if (t + 3 < dl) {
            const float* hq = hp + (size_t)(t + 3) * DDIM;
            const float* gq = gp + (size_t)(t + 3) * DDIM;
            *(float4*)h3 = *(const float4*)hq;
            *(float4*)(h3 + 4) = *(const float4*)(hq + 4);
            *(float4*)g3 = *(const float4*)gq;
            *(float4*)(g3 + 4) = *(const float4*)(gq + 4);
        }
        do_step(t, h0, g0);
        do_step(t + 1, h1, g1);
#pragma unroll
        for (int e = 0; e < 8; e++) {
            h0[e] = h2[e]; g0[e] = g2[e];
            h1[e] = h3[e]; g1[e] = g3[e];
        }
    }
    if (t < dl) do_step(t, h0, g0);
}

// ======================= launch =======================
extern "C" void kernel_launch(void* const* d_in, const int* in_sizes, int n_in,
                              void* d_out, int out_size) {
    const float* sent      = (const float*)d_in[0];
    const float* fc_w      = (const float*)d_in[1];
    const float* fc_b      = (const float*)d_in[2];
    const float* w_content = (const float*)d_in[3];
    const float* W_sal     = (const float*)d_in[4];
    const float* W_nov     = (const float*)d_in[5];
    const float* abs_e     = (const float*)d_in[6];
    const float* rel_e     = (const float*)d_in[7];
    const float* w_abs     = (const float*)d_in[8];
    const float* w_rel     = (const float*)d_in[9];
    const float* bias      = (const float*)d_in[10];
    const int*   doc_lens  = (const int*)d_in[11];
    const int B = in_sizes[11];
    const int rows_max = B * LMAX;

    cudaFuncSetAttribute(ugemm_kernel,
                         cudaFuncAttributeMaxDynamicSharedMemorySize, U_TOTAL);
    cudaFuncSetAttribute(gemm3_kernel,
                         cudaFuncAttributeMaxDynamicSharedMemorySize, GSM3_TOTAL);

    __nv_bfloat16 *W1h, *W1l, *W2h, *W2l, *W3h, *W3l;
    float *docs, *u, *G;
    int *rowmap;
    cudaGetSymbolAddress((void**)&W1h, g_W1h);
    cudaGetSymbolAddress((void**)&W1l, g_W1l);
    cudaGetSymbolAddress((void**)&W2h, g_W2h);
    cudaGetSymbolAddress((void**)&W2l, g_W2l);
    cudaGetSymbolAddress((void**)&W3h, g_W3h);
    cudaGetSymbolAddress((void**)&W3l, g_W3l);
    cudaGetSymbolAddress((void**)&docs, g_docs);
    cudaGetSymbolAddress((void**)&u, g_u);
    cudaGetSymbolAddress((void**)&G, g_G);
    cudaGetSymbolAddress((void**)&rowmap, g_rowmap);

    static cudaStream_t s_side = nullptr;
    static cudaEvent_t ev_fork = nullptr, ev_join = nullptr;
    if (!s_side) {
        cudaStreamCreateWithFlags(&s_side, cudaStreamNonBlocking);
        cudaEventCreateWithFlags(&ev_fork, cudaEventDisableTiming);
        cudaEventCreateWithFlags(&ev_join, cudaEventDisableTiming);
    }

    // main: scan, prep_all
    scan_kernel<<<1, 256>>>(doc_lens, B, abs_e, rel_e, w_abs, w_rel);
    prep_all_kernel<<<dim3(256, 4), 256>>>(fc_w, W_sal, W_nov, doc_lens, B);

    cudaEventRecord(ev_fork, 0);
    cudaStreamWaitEvent(s_side, ev_fork, 0);

    // main: gemm3 enqueued BEFORE side kernels (deps unchanged; shifts ncu target)
    dim3 ggrid((rows_max + 127) / 128, 2);
    gemm3_kernel<<<ggrid, 256, GSM3_TOTAL>>>(sent, W3h, W3l, G, rowmap);

    // side: mean, ugemm (hidden under gemm3)
    mean_kernel<<<B, 256, 0, s_side>>>(sent, doc_lens);
    ugemm_kernel<<<(B + 63) / 64, 256, U_TOTAL, s_side>>>(
        docs, W1h, W1l, W2h, W2l, fc_b, w_content, u, B);
    cudaEventRecord(ev_join, s_side);

    cudaStreamWaitEvent(0, ev_join, 0);
    recur_kernel<<<(B + 7) / 8, 256>>>(sent, bias, doc_lens, B, (float*)d_out);
}

// round 14
// speedup vs baseline: 1.1595x; 1.1595x over previous
#include <cuda_runtime.h>
#include <cuda_bf16.h>
#include <math.h>
#include <cstdint>

#define B_MAX 2048
#define LMAX 100
#define DDIM 256
#define POS_DIM 50

__device__ int   g_offs[B_MAX];
__device__ int   g_perm[B_MAX];
__device__ int   g_total_rows;
__device__ int   g_rowmap[(size_t)B_MAX * LMAX];
__device__ float g_abs_vals[LMAX];
__device__ float g_rel_vals[32];
__device__ float g_docs[(size_t)B_MAX * DDIM];
__device__ float g_u[(size_t)B_MAX * DDIM];
__device__ float g_G[(size_t)B_MAX * LMAX * DDIM];
__device__ __nv_bfloat16 g_W1h[DDIM * DDIM], g_W1l[DDIM * DDIM]; // fc_w
__device__ __nv_bfloat16 g_W2h[DDIM * DDIM], g_W2l[DDIM * DDIM]; // W_sal
__device__ __nv_bfloat16 g_W3h[DDIM * DDIM], g_W3l[DDIM * DDIM]; // W_nov^T

__device__ __forceinline__ uint32_t smem_u32(const void* p) {
    uint32_t a;
    asm("{ .reg .u64 t; cvta.to.shared.u64 t, %1; cvt.u32.u64 %0, t; }"
        : "=r"(a) : "l"(p));
    return a;
}
#define LDSM4(r, addr) \
    asm volatile("ldmatrix.sync.aligned.m8n8.x4.shared.b16 {%0,%1,%2,%3}, [%4];" \
        : "=r"((r)[0]), "=r"((r)[1]), "=r"((r)[2]), "=r"((r)[3]) : "r"(addr))
#define MMA_BF16(c, a, b0, b1) \
    asm volatile("mma.sync.aligned.m16n8k16.row.col.f32.bf16.bf16.f32 " \
        "{%0,%1,%2,%3},{%4,%5,%6,%7},{%8,%9},{%0,%1,%2,%3};" \
        : "+f"((c)[0]), "+f"((c)[1]), "+f"((c)[2]), "+f"((c)[3]) \
        : "r"((a)[0]), "r"((a)[1]), "r"((a)[2]), "r"((a)[3]), "r"(b0), "r"(b1))

__device__ __forceinline__ void split_store(char* hi_p, char* lo_p, float2 v) {
    __nv_bfloat162 h = __float22bfloat162_rn(v);
    float2 f = __bfloat1622float2(h);
    __nv_bfloat162 l = __float22bfloat162_rn(make_float2(v.x - f.x, v.y - f.y));
    *(__nv_bfloat162*)hi_p = h;
    *(__nv_bfloat162*)lo_p = l;
}

// ===== scan: offsets, total, global length sort, position dots =====
__global__ void scan_kernel(const int* __restrict__ dl, int B,
                            const float* __restrict__ abs_e,
                            const float* __restrict__ rel_e,
                            const float* __restrict__ w_abs,
                            const float* __restrict__ w_rel) {
    __shared__ int sh[B_MAX];
    __shared__ int wsum[8];
    __shared__ int hist[LMAX + 1];
    __shared__ int hstart[LMAX + 1];
    int t = threadIdx.x;
    for (int i = t; i < B_MAX; i += 256) sh[i] = (i < B) ? dl[i] : 0;
    if (t <= LMAX) hist[t] = 0;
    __syncthreads();
    int base = t * 8;
    int ex[8]; int run = 0;
#pragma unroll
    for (int k = 0; k < 8; k++) { ex[k] = run; run += sh[base + k]; }
    int lane = t & 31, w = t >> 5;
    int inc = run;
#pragma unroll
    for (int st = 1; st < 32; st <<= 1) {
        int x = __shfl_up_sync(0xffffffffu, inc, st);
        if (lane >= st) inc += x;
    }
    if (lane == 31) wsum[w] = inc;
    for (int i = t; i < B; i += 256) {
        int d = sh[i]; d = (d < 0) ? 0 : (d > LMAX ? LMAX : d);
        atomicAdd(&hist[d], 1);
    }
    __syncthreads();
    int wbase = 0;
    for (int i = 0; i < w; i++) wbase += wsum[i];
    int chunk_ex = wbase + inc - run;
#pragma unroll
    for (int k = 0; k < 8; k++)
        if (base + k < B) g_offs[base + k] = chunk_ex + ex[k];
    if (t == 0) {
        int tot = 0;
        for (int i = 0; i < 8; i++) tot += wsum[i];
        g_total_rows = tot;
        int running = 0;
        for (int d = LMAX; d >= 0; d--) { hstart[d] = running; running += hist[d]; }
    }
    __syncthreads();
    for (int i = t; i < B; i += 256) {
        int d = sh[i]; d = (d < 0) ? 0 : (d > LMAX ? LMAX : d);
        int pos = atomicAdd(&hstart[d], 1);
        g_perm[pos] = i;
    }
    if (t < LMAX) {
        float a = 0.f;
        for (int i = 0; i < POS_DIM; i++) a += abs_e[t * POS_DIM + i] * w_abs[i];
        g_abs_vals[t] = a;
    } else if (t >= 128 && t < 153) {
        int s = t - 128;
        float a = 0.f;
        for (int i = 0; i < POS_DIM; i++) a += rel_e[s * POS_DIM + i] * w_rel[i];
        g_rel_vals[s] = a;
    }
}

// ===== prep_W: weight split only (independent of doc_lens) =====
__global__ void prep_w_kernel(const float* __restrict__ fc_w,
                              const float* __restrict__ W_sal,
                              const float* __restrict__ W_nov) {
    int idx = blockIdx.x * 256 + threadIdx.x;
    int y = blockIdx.y;
    if (y == 0) {
        int n = idx >> 8, k = idx & 255;
        float w = W_nov[k * DDIM + n];
        __nv_bfloat16 h = __float2bfloat16_rn(w);
        g_W3h[n * DDIM + k] = h;
        g_W3l[n * DDIM + k] = __float2bfloat16_rn(w - __bfloat162float(h));
    } else if (y == 1) {
        float w = fc_w[idx];
        __nv_bfloat16 h = __float2bfloat16_rn(w);
        g_W1h[idx] = h;
        g_W1l[idx] = __float2bfloat16_rn(w - __bfloat162float(h));
    } else {
        float w = W_sal[idx];
        __nv_bfloat16 h = __float2bfloat16_rn(w);
        g_W2h[idx] = h;
        g_W2l[idx] = __float2bfloat16_rn(w - __bfloat162float(h));
    }
}

// ===== rowmap expand (needs g_offs) =====
__global__ void rowmap_kernel(const int* __restrict__ dl, int B) {
    int idx = blockIdx.x * 256 + threadIdx.x;
    int b = idx >> 5, j = idx & 31;
    if (b < B) {
        int n = dl[b], off = g_offs[b];
        for (int k = j; k < n; k += 32)
            g_rowmap[off + k] = b * LMAX + k;
    }
}

// ===== masked mean (float4, 4 rows in flight) =====
__global__ void __launch_bounds__(256) mean_kernel(const float* __restrict__ sent,
                                                   const int* __restrict__ dl) {
    __shared__ float4 part[4][64];
    int b = blockIdx.x, tid = threadIdx.x;
    int n = dl[b];
    int c4 = tid & 63, rq = tid >> 6;
    const float4* sp = (const float4*)(sent + (size_t)b * LMAX * DDIM);
    float4 a = make_float4(0.f, 0.f, 0.f, 0.f);
    for (int t = rq; t < n; t += 4) {
        float4 v = sp[t * 64 + c4];
        a.x += v.x; a.y += v.y; a.z += v.z; a.w += v.w;
    }
    part[rq][c4] = a;
    __syncthreads();
    if (tid < 64) {
        float4 r0 = part[0][tid], r1 = part[1][tid], r2 = part[2][tid], r3 = part[3][tid];
        float inv = __fdiv_rn(1.f, (float)n);
        float4 o;
        o.x = (r0.x + r1.x + r2.x + r3.x) * inv;
        o.y = (r0.y + r1.y + r2.y + r3.y) * inv;
        o.z = (r0.z + r1.z + r2.z + r3.z) * inv;
        o.w = (r0.w + r1.w + r2.w + r3.w) * inv;
        *(float4*)&g_docs[(size_t)b * DDIM + tid * 4] = o;
    }
}

// ===== fused doc+u kernel =====
#define U_DOC_HI 0
#define U_DOC_LO 33792
#define U_A1_HI  67584
#define U_A1_LO  76800
#define U_B_HI   86016
#define U_B_LO   104448
#define U_TOTAL  122880

__global__ void __launch_bounds__(256) ugemm_kernel(
    const float* __restrict__ docs,
    const __nv_bfloat16* __restrict__ W1h, const __nv_bfloat16* __restrict__ W1l,
    const __nv_bfloat16* __restrict__ W2h, const __nv_bfloat16* __restrict__ W2l,
    const float* __restrict__ fc_b, const float* __restrict__ w_content,
    float* __restrict__ u_out, int M)
{
    const int m0 = blockIdx.x * 64;
    if (m0 >= M) return;
    extern __shared__ char sm[];
    const uint32_t sb = smem_u32(sm);
    const int tid = threadIdx.x, lane = tid & 31, wid = tid >> 5;
    const int wm = wid & 1, wn = wid >> 1;
    const int alr = lane & 15, alc = (lane & 16) >> 1;
    const int blr = (lane & 7) | ((lane >> 1) & 8), blc = lane & 8;
    const int gID = lane >> 2, tg = lane & 3;
    const uint32_t a1_base = sb + U_A1_HI + (uint32_t)((wm * 32 + alr) * 144 + alc * 2);
    const uint32_t a2_base = sb + U_DOC_HI + (uint32_t)((wm * 32 + alr) * 528 + alc * 2);
    const uint32_t b_base  = sb + U_B_HI + (uint32_t)((wn * 32 + blr) * 144 + blc * 2);

    for (int nh = 0; nh < 2; nh++) {
        float c[2][4][4];
#pragma unroll
        for (int mt = 0; mt < 2; mt++)
#pragma unroll
            for (int nf = 0; nf < 4; nf++)
#pragma unroll
                for (int r = 0; r < 4; r++) c[mt][nf][r] = 0.f;

        for (int ch = 0; ch < 4; ch++) {
            __syncthreads();
#pragma unroll
            for (int i = 0; i < 4; i++) {
                int idx = tid + i * 256;
                int m = idx >> 4, kq = idx & 15;
                float4 v = make_float4(0.f, 0.f, 0.f, 0.f);
                if (m0 + m < M)
                    v = *(const float4*)&docs[(size_t)(m0 + m) * DDIM + ch * 64 + kq * 4];
                split_store(sm + U_A1_HI + m * 144 + kq * 8,
                            sm + U_A1_LO + m * 144 + kq * 8, make_float2(v.x, v.y));
                split_store(sm + U_A1_HI + m * 144 + kq * 8 + 4,
                            sm + U_A1_LO + m * 144 + kq * 8 + 4, make_float2(v.z, v.w));
            }
#pragma unroll
            for (int i = 0; i < 4; i++) {
                int idx = tid + i * 256;
                int n = idx >> 3, k4 = idx & 7;
                *(float4*)(sm + U_B_HI + n * 144 + k4 * 16) =
                    *(const float4*)&W1h[(size_t)(nh * 128 + n) * DDIM + ch * 64 + k4 * 8];
                *(float4*)(sm + U_B_LO + n * 144 + k4 * 16) =
                    *(const float4*)&W1l[(size_t)(nh * 128 + n) * DDIM + ch * 64 + k4 * 8];
            }
            __syncthreads();
#pragma unroll
            for (int ks = 0; ks < 4; ks++) {
                uint32_t ah[2][4], al[2][4], bh[2][4], bl[2][4];
#pragma unroll
                for (int mt = 0; mt < 2; mt++) {
                    LDSM4(ah[mt], a1_base + mt * 2304 + ks * 32);
                    LDSM4(al[mt], a1_base + 9216u + mt * 2304 + ks * 32);
                }
#pragma unroll
                for (int nt = 0; nt < 2; nt++) {
                    LDSM4(bh[nt], b_base + nt * 2304 + ks * 32);
                    LDSM4(bl[nt], b_base + 18432u + nt * 2304 + ks * 32);
                }
#pragma unroll
                for (int mt = 0; mt < 2; mt++)
#pragma unroll
                    for (int nf = 0; nf < 4; nf++) {
                        MMA_BF16(c[mt][nf], ah[mt], bh[nf >> 1][(nf & 1) * 2],
                                 bh[nf >> 1][(nf & 1) * 2 + 1]);
                        MMA_BF16(c[mt][nf], ah[mt], bl[nf >> 1][(nf & 1) * 2],
                                 bl[nf >> 1][(nf & 1) * 2 + 1]);
                        MMA_BF16(c[mt][nf], al[mt], bh[nf >> 1][(nf & 1) * 2],
                                 bh[nf >> 1][(nf & 1) * 2 + 1]);
                    }
            }
        }
#pragma unroll
        for (int mt = 0; mt < 2; mt++)
#pragma unroll
            for (int nf = 0; nf < 4; nf++) {
                int row = wm * 32 + mt * 16 + gID;
                int kcol = nh * 128 + wn * 32 + nf * 8 + tg * 2;
                float b0v = fc_b[kcol], b1v = fc_b[kcol + 1];
                float2 v0 = make_float2(tanhf(c[mt][nf][0] + b0v),
                                        tanhf(c[mt][nf][1] + b1v));
                split_store(sm + U_DOC_HI + row * 528 + kcol * 2,
                            sm + U_DOC_LO + row * 528 + kcol * 2, v0);
                float2 v1 = make_float2(tanhf(c[mt][nf][2] + b0v),
                                        tanhf(c[mt][nf][3] + b1v));
                split_store(sm + U_DOC_HI + (row + 8) * 528 + kcol * 2,
                            sm + U_DOC_LO + (row + 8) * 528 + kcol * 2, v1);
            }
    }
    __syncthreads();

    for (int nh = 0; nh < 2; nh++) {
        float c[2][4][4];
#pragma unroll
        for (int mt = 0; mt < 2; mt++)
#pragma unroll
            for (int nf = 0; nf < 4; nf++)
#pragma unroll
                for (int r = 0; r < 4; r++) c[mt][nf][r] = 0.f;

        for (int ch = 0; ch < 4; ch++) {
            __syncthreads();
#pragma unroll
            for (int i = 0; i < 4; i++) {
                int idx = tid + i * 256;
                int n = idx >> 3, k4 = idx & 7;
                *(float4*)(sm + U_B_HI + n * 144 + k4 * 16) =
                    *(const float4*)&W2h[(size_t)(nh * 128 + n) * DDIM + ch * 64 + k4 * 8];
                *(float4*)(sm + U_B_LO + n * 144 + k4 * 16) =
                    *(const float4*)&W2l[(size_t)(nh * 128 + n) * DDIM + ch * 64 + k4 * 8];
            }
            __syncthreads();
#pragma unroll
            for (int ks = 0; ks < 4; ks++) {
                const uint32_t ka = (uint32_t)((ch * 64 + ks * 16) * 2);
                uint32_t ah[2][4], al[2][4], bh[2][4], bl[2][4];
#pragma unroll
                for (int mt = 0; mt < 2; mt++) {
                    LDSM4(ah[mt], a2_base + mt * 8448 + ka);
                    LDSM4(al[mt], a2_base + 33792u + mt * 8448 + ka);
                }
#pragma unroll
                for (int nt = 0; nt < 2; nt++) {
                    LDSM4(bh[nt], b_base + nt * 2304 + ks * 32);
                    LDSM4(bl[nt], b_base + 18432u + nt * 2304 + ks * 32);
                }
#pragma unroll
                for (int mt = 0; mt < 2; mt++)
#pragma unroll
                    for (int nf = 0; nf < 4; nf++) {
                        MMA_BF16(c[mt][nf], ah[mt], bh[nf >> 1][(nf & 1) * 2],
                                 bh[nf >> 1][(nf & 1) * 2 + 1]);
                        MMA_BF16(c[mt][nf], ah[mt], bl[nf >> 1][(nf & 1) * 2],
                                 bl[nf >> 1][(nf & 1) * 2 + 1]);
                        MMA_BF16(c[mt][nf], al[mt], bh[nf >> 1][(nf & 1) * 2],
                                 bh[nf >> 1][(nf & 1) * 2 + 1]);
                    }
            }
        }
#pragma unroll
        for (int mt = 0; mt < 2; mt++)
#pragma unroll
            for (int nf = 0; nf < 4; nf++) {
                int row = wm * 32 + mt * 16 + gID;
                int n = nh * 128 + wn * 32 + nf * 8 + tg * 2;
                float w0 = w_content[n], w1 = w_content[n + 1];
                if (m0 + row < M)
                    *(float2*)&u_out[(size_t)(m0 + row) * DDIM + n] =
                        make_float2(c[mt][nf][0] + w0, c[mt][nf][1] + w1);
                if (m0 + row + 8 < M)
                    *(float2*)&u_out[(size_t)(m0 + row + 8) * DDIM + n] =
                        make_float2(c[mt][nf][2] + w0, c[mt][nf][3] + w1);
            }
    }
}

// ===== big GEMM (round-12 best): 128x128 CTA tile, 64x32 warp tile =====
#define AS_HI 0
#define AS_LO 18432
#define BS_HI 36864
#define BS_LO 55296
#define GSM3_TOTAL 73728

__global__ void __launch_bounds__(256, 2) gemm3_kernel(
    const float* __restrict__ A, const __nv_bfloat16* __restrict__ Bh,
    const __nv_bfloat16* __restrict__ Bl, float* __restrict__ C,
    const int* __restrict__ row_map)
{
    const int M = g_total_rows;
    const int gm0 = blockIdx.x * 128;
    if (gm0 >= M) return;
    extern __shared__ char sm[];
    const uint32_t sb = smem_u32(sm);
    const int tid = threadIdx.x, lane = tid & 31, wid = tid >> 5;
    const int wm = wid & 1, wn = wid >> 1;
    const int n0 = blockIdx.y * 128;

    const int alr = lane & 15;
    const int alc = (lane & 16) >> 1;
    const int blr = (lane & 7) | ((lane >> 1) & 8);
    const int blc = lane & 8;
    const uint32_t a_base = sb + AS_HI + (uint32_t)(((wm * 64 + alr) * 72 + alc) * 2);
    const uint32_t b_base = sb + BS_HI + (uint32_t)(((wn * 32 + blr) * 72 + blc) * 2);

    float c[4][4][4];
#pragma unroll
    for (int mt = 0; mt < 4; mt++)
#pragma unroll
        for (int nf = 0; nf < 4; nf++)
#pragma unroll
            for (int r = 0; r < 4; r++) c[mt][nf][r] = 0.f;

    for (int ch = 0; ch < 4; ch++) {
        const int k0 = ch * 64;
#pragma unroll
        for (int i = 0; i < 8; i++) {
            int idx = tid + i * 256;
            int m = idx >> 4, kq = idx & 15;
            float4 v = make_float4(0.f, 0.f, 0.f, 0.f);
            int gm = gm0 + m;
            if (gm < M)
                v = *(const float4*)&A[(size_t)row_map[gm] * DDIM + k0 + kq * 4];
            split_store(sm + AS_HI + m * 144 + kq * 8,
                        sm + AS_LO + m * 144 + kq * 8, make_float2(v.x, v.y));
            split_store(sm + AS_HI + m * 144 + kq * 8 + 4,
                        sm + AS_LO + m * 144 + kq * 8 + 4, make_float2(v.z, v.w));
        }
#pragma unroll
        for (int i = 0; i < 4; i++) {
            int idx = tid + i * 256;
            int n = idx >> 3, k4 = idx & 7;
            *(float4*)(sm + BS_HI + n * 144 + k4 * 16) =
                *(const float4*)&Bh[(size_t)(n0 + n) * DDIM + k0 + k4 * 8];
            *(float4*)(sm + BS_LO + n * 144 + k4 * 16) =
                *(const float4*)&Bl[(size_t)(n0 + n) * DDIM + k0 + k4 * 8];
        }
        __syncthreads();
#pragma unroll
        for (int ks = 0; ks < 4; ks++) {
            uint32_t ah[4][4], al[4][4], bh[2][4], bl[2][4];
#pragma unroll
            for (int mt = 0; mt < 4; mt++)
                LDSM4(ah[mt], a_base + mt * 2304 + ks * 32);
#pragma unroll
            for (int nt = 0; nt < 2; nt++) {
                LDSM4(bh[nt], b_base + nt * 2304 + ks * 32);
                LDSM4(bl[nt], b_base + 18432u + nt * 2304 + ks * 32);
            }
#pragma unroll
            for (int mt = 0; mt < 4; mt++)
#pragma unroll
                for (int nf = 0; nf < 4; nf++) {
                    MMA_BF16(c[mt][nf], ah[mt], bh[nf >> 1][(nf & 1) * 2],
                             bh[nf >> 1][(nf & 1) * 2 + 1]);
                    MMA_BF16(c[mt][nf], ah[mt], bl[nf >> 1][(nf & 1) * 2],
                             bl[nf >> 1][(nf & 1) * 2 + 1]);
                }
#pragma unroll
            for (int mt = 0; mt < 4; mt++)
                LDSM4(al[mt], a_base + 18432u + mt * 2304 + ks * 32);
#pragma unroll
            for (int mt = 0; mt < 4; mt++)
#pragma unroll
                for (int nf = 0; nf < 4; nf++)
                    MMA_BF16(c[mt][nf], al[mt], bh[nf >> 1][(nf & 1) * 2],
                             bh[nf >> 1][(nf & 1) * 2 + 1]);
        }
        __syncthreads();
    }

    float* stage = (float*)sm;
    const int gID = lane >> 2, tg = lane & 3;
    for (int mh = 0; mh < 2; mh++) {
        if (wm == mh) {
#pragma unroll
            for (int mt = 0; mt < 4; mt++)
#pragma unroll
                for (int nf = 0; nf < 4; nf++) {
                    int r = mt * 16 + gID;
                    int cc = wn * 32 + nf * 8 + tg * 2;
                    *(float2*)&stage[r * 132 + cc] =
                        make_float2(c[mt][nf][0], c[mt][nf][1]);
                    *(float2*)&stage[(r + 8) * 132 + cc] =
                        make_float2(c[mt][nf][2], c[mt][nf][3]);
                }
        }
        __syncthreads();
#pragma unroll
        for (int i = 0; i < 8; i++) {
            int idx = tid + i * 256;
            int r = idx >> 5, c4 = idx & 31;
            int grow = gm0 + mh * 64 + r;
            if (grow < M)
                *(float4*)&C[(size_t)grow * DDIM + n0 + c4 * 4] =
                    *(float4*)&stage[r * 132 + c4 * 4];
        }
        __syncthreads();
    }
}

// ===== fast tanh =====
__device__ __forceinline__ float fast_tanh(float x) {
    float e = __expf(2.f * x);
    return 1.f - __fdividef(2.f, e + 1.f);
}

// ===== warp-per-doc recurrence (length-sorted), 2-pair prefetch =====
__global__ void __launch_bounds__(256) recur_kernel(
    const float* __restrict__ sent, const float* __restrict__ bias,
    const int* __restrict__ doc_lens, int B, float* __restrict__ out)
{
    __shared__ float sA[LMAX];
    __shared__ float sR[32];
    const int tid = threadIdx.x, lane = tid & 31, wid = tid >> 5;
    if (tid < LMAX) sA[tid] = g_abs_vals[tid];
    if (tid < 32) sR[tid] = g_rel_vals[tid];
    __syncthreads();

    const int gid = blockIdx.x * 8 + wid;
    if (gid >= B) return;
    const int b = g_perm[gid];
    const int dl = doc_lens[b];
    const float dlf = (float)dl;
    const int off = g_offs[b];
    const float* hp = sent + (size_t)b * LMAX * DDIM + lane * 8;
    const float* gp = g_G + (size_t)off * DDIM + lane * 8;
    const float b0 = bias[0];

    float u[8];
    {
        const float* up = g_u + (size_t)b * DDIM + lane * 8;
        *(float4*)u = *(const float4*)up;
        *(float4*)(u + 4) = *(const float4*)(up + 4);
    }
    float s[8] = {0.f, 0.f, 0.f, 0.f, 0.f, 0.f, 0.f, 0.f};

    auto do_step = [&](int t, const float* hc, const float* gc) {
        float v0 = 0.f, v1 = 0.f;
#pragma unroll
        for (int e = 0; e < 4; e++)
            v0 += hc[e] * u[e] - gc[e] * fast_tanh(s[e]);
#pragma unroll
        for (int e = 4; e < 8; e++)
            v1 += hc[e] * u[e] - gc[e] * fast_tanh(s[e]);
        float v = v0 + v1;
#pragma unroll
        for (int st = 16; st; st >>= 1) v += __shfl_xor_sync(0xffffffffu, v, st);
        int ri = (int)rintf(__fdiv_rn((float)(t + 1) * 9.0f, dlf));
        float x = v + sA[t] + sR[ri] + b0;
        float p = __fdividef(1.f, 1.f + __expf(-x));
#pragma unroll
        for (int e = 0; e < 8; e++) s[e] = fmaf(p, hc[e], s[e]);
        if (lane == 0) out[off + t] = p;
    };

    float h0[8], g0[8], h1[8], g1[8];
    *(float4*)h0 = *(const float4*)hp;
    *(float4*)(h0 + 4) = *(const float4*)(hp + 4);
    *(float4*)g0 = *(const float4*)gp;
    *(float4*)(g0 + 4) = *(const float4*)(gp + 4);
    if (dl > 1) {
        *(float4*)h1 = *(const float4*)(hp + DDIM);
        *(float4*)(h1 + 4) = *(const float4*)(hp + DDIM + 4);
        *(float4*)g1 = *(const float4*)(gp + DDIM);
        *(float4*)(g1 + 4) = *(const float4*)(gp + DDIM + 4);
    }

    int t = 0;
    for (; t + 1 < dl; t += 2) {
        float h2[8], g2[8], h3[8], g3[8];
        if (t + 2 < dl) {
            const float* hq = hp + (size_t)(t + 2) * DDIM;
            const float* gq = gp + (size_t)(t + 2) * DDIM;
            *(float4*)h2 = *(const float4*)hq;
            *(float4*)(h2 + 4) = *(const float4*)(hq + 4);
            *(float4*)g2 = *(const float4*)gq;
            *(float4*)(g2 + 4) = *(const float4*)(gq + 4);
        }
        if (t + 3 < dl) {
            const float* hq = hp + (size_t)(t + 3) * DDIM;
            const float* gq = gp + (size_t)(t + 3) * DDIM;
            *(float4*)h3 = *(const float4*)hq;
            *(float4*)(h3 + 4) = *(const float4*)(hq + 4);
            *(float4*)g3 = *(const float4*)gq;
            *(float4*)(g3 + 4) = *(const float4*)(gq + 4);
        }
        do_step(t, h0, g0);
        do_step(t + 1, h1, g1);
#pragma unroll
        for (int e = 0; e < 8; e++) {
            h0[e] = h2[e]; g0[e] = g2[e];
            h1[e] = h3[e]; g1[e] = g3[e];
        }
    }
    if (t < dl) do_step(t, h0, g0);
}

// ======================= launch =======================
extern "C" void kernel_launch(void* const* d_in, const int* in_sizes, int n_in,
                              void* d_out, int out_size) {
    const float* sent      = (const float*)d_in[0];
    const float* fc_w      = (const float*)d_in[1];
    const float* fc_b      = (const float*)d_in[2];
    const float* w_content = (const float*)d_in[3];
    const float* W_sal     = (const float*)d_in[4];
    const float* W_nov     = (const float*)d_in[5];
    const float* abs_e     = (const float*)d_in[6];
    const float* rel_e     = (const float*)d_in[7];
    const float* w_abs     = (const float*)d_in[8];
    const float* w_rel     = (const float*)d_in[9];
    const float* bias      = (const float*)d_in[10];
    const int*   doc_lens  = (const int*)d_in[11];
    const int B = in_sizes[11];
    const int rows_max = B * LMAX;

    cudaFuncSetAttribute(ugemm_kernel,
                         cudaFuncAttributeMaxDynamicSharedMemorySize, U_TOTAL);
    cudaFuncSetAttribute(gemm3_kernel,
                         cudaFuncAttributeMaxDynamicSharedMemorySize, GSM3_TOTAL);

    __nv_bfloat16 *W1h, *W1l, *W2h, *W2l, *W3h, *W3l;
    float *docs, *u, *G;
    int *rowmap;
    cudaGetSymbolAddress((void**)&W1h, g_W1h);
    cudaGetSymbolAddress((void**)&W1l, g_W1l);
    cudaGetSymbolAddress((void**)&W2h, g_W2h);
    cudaGetSymbolAddress((void**)&W2l, g_W2l);
    cudaGetSymbolAddress((void**)&W3h, g_W3h);
    cudaGetSymbolAddress((void**)&W3l, g_W3l);
    cudaGetSymbolAddress((void**)&docs, g_docs);
    cudaGetSymbolAddress((void**)&u, g_u);
    cudaGetSymbolAddress((void**)&G, g_G);
    cudaGetSymbolAddress((void**)&rowmap, g_rowmap);

    static cudaStream_t s_side = nullptr;
    static cudaEvent_t ev_fork = nullptr, ev_w3 = nullptr, ev_join = nullptr;
    if (!s_side) {
        cudaStreamCreateWithFlags(&s_side, cudaStreamNonBlocking);
        cudaEventCreateWithFlags(&ev_fork, cudaEventDisableTiming);
        cudaEventCreateWithFlags(&ev_w3, cudaEventDisableTiming);
        cudaEventCreateWithFlags(&ev_join, cudaEventDisableTiming);
    }

    // fork side stream FIRST (event from origin stream — legal capture fork)
    cudaEventRecord(ev_fork, 0);
    cudaStreamWaitEvent(s_side, ev_fork, 0);

    // side: weight prep (independent of doc_lens) -> mean -> ugemm
    prep_w_kernel<<<dim3(256, 3), 256, 0, s_side>>>(fc_w, W_sal, W_nov);
    cudaEventRecord(ev_w3, s_side);
    mean_kernel<<<B, 256, 0, s_side>>>(sent, doc_lens);
    ugemm_kernel<<<(B + 63) / 64, 256, U_TOTAL, s_side>>>(
        docs, W1h, W1l, W2h, W2l, fc_b, w_content, u, B);
    cudaEventRecord(ev_join, s_side);

    // main: scan -> rowmap (concurrent with prep_w) -> (wait W3) gemm3 -> recur
    scan_kernel<<<1, 256>>>(doc_lens, B, abs_e, rel_e, w_abs, w_rel);
    rowmap_kernel<<<(B * 32 + 255) / 256, 256>>>(doc_lens, B);
    cudaStreamWaitEvent(0, ev_w3, 0);
    dim3 ggrid((rows_max + 127) / 128, 2);
    gemm3_kernel<<<ggrid, 256, GSM3_TOTAL>>>(sent, W3h, W3l, G, rowmap);
    cudaStreamWaitEvent(0, ev_join, 0);
    recur_kernel<<<(B + 7) / 8, 256>>>(sent, bias, doc_lens, B, (float*)d_out);
}